// round 5
// baseline (speedup 1.0000x reference)
#include <cuda_runtime.h>

#define S_LEN 2048
#define B_SZ  8192
#define GPC   8                 // groups (batch elements) per CTA
#define TPB   (GPC * 8)         // 64 threads per CTA
#define NCTA  (B_SZ / GPC)      // 1024 CTAs

typedef unsigned long long u64;

__device__ float g_partials[NCTA];

__device__ __forceinline__ float ex2f(float x){ float y; asm("ex2.approx.f32 %0, %1;" : "=f"(y) : "f"(x)); return y; }
__device__ __forceinline__ float lg2f(float x){ float y; asm("lg2.approx.f32 %0, %1;" : "=f"(y) : "f"(x)); return y; }
__device__ __forceinline__ float tanhfast(float x){ float y; asm("tanh.approx.f32 %0, %1;" : "=f"(y) : "f"(x)); return y; }

// packed f32x2 fma (Blackwell): d = a*b + c elementwise on (lo,hi)
__device__ __forceinline__ u64 fma2(u64 a, u64 b, u64 c){
    u64 d; asm("fma.rn.f32x2 %0, %1, %2, %3;" : "=l"(d) : "l"(a), "l"(b), "l"(c)); return d;
}
__device__ __forceinline__ u64 pack2(float lo, float hi){
    u64 d; asm("mov.b64 %0, {%1, %2};" : "=l"(d) : "f"(lo), "f"(hi)); return d;
}
__device__ __forceinline__ float hadd2(u64 v){
    float lo, hi; asm("mov.b64 {%0, %1}, %2;" : "=f"(lo), "=f"(hi) : "l"(v)); return lo + hi;
}

__global__ __launch_bounds__(TPB) void gru_kernel(
    const int* __restrict__ x_batch,
    const float* __restrict__ Wir, const float* __restrict__ bir,
    const float* __restrict__ Wiz, const float* __restrict__ biz,
    const float* __restrict__ Win, const float* __restrict__ bin_,
    const float* __restrict__ Whr, const float* __restrict__ bhr,
    const float* __restrict__ Whz, const float* __restrict__ bhz,
    const float* __restrict__ Whn, const float* __restrict__ bhn,
    const float* __restrict__ Wout, const float* __restrict__ bout)
{
    // x-projection LUTs per count value v (0..9, padded to 16). R/Z entries
    // pre-packed as (val, 0) f32x2 to seed packed accumulators with one
    // LDS.64. Row stride 9 to spread banks across groups.
    __shared__ u64   lutR2[16][9];
    __shared__ u64   lutZ2[16][9];
    __shared__ float lutN [16][9];
    __shared__ float red[GPC];

    const int tid  = threadIdx.x;
    const int lane = tid & 7;            // hidden-unit row this thread owns
    const int g    = tid >> 3;           // group within CTA
    const int b    = blockIdx.x * GPC + g;
    const unsigned FULL = 0xffffffffu;

    const float L2E = 1.4426950408889634f;   // log2(e) (softmax fold)

    // ---- build LUTs (bits MSB-first). sigmoid(x)=0.5+0.5*tanh(x/2): fold 0.5 in.
    for (int i = tid; i < 16 * 8; i += TPB) {
        const int v = i >> 3;
        const int l = i & 7;
        float sr = 0.f, sz = 0.f, sn = 0.f;
        #pragma unroll
        for (int k = 0; k < 4; ++k)
            if ((v >> (3 - k)) & 1) {
                sr += Wir[l * 4 + k];
                sz += Wiz[l * 4 + k];
                sn += Win[l * 4 + k];
            }
        lutR2[v][l] = pack2((sr + bir[l] + bhr[l]) * 0.5f, 0.f);
        lutZ2[v][l] = pack2((sz + biz[l] + bhz[l]) * 0.5f, 0.f);
        lutN [v][l] = sn + bin_[l];
    }

    // ---- per-thread weights, packed across k-pairs ----
    u64 wr2[4], wz2[4], wn2[4], wa2[4], wb2[4];
    #pragma unroll
    for (int j = 0; j < 4; ++j) {
        wr2[j] = pack2(Whr[lane * 8 + 2 * j] * 0.5f, Whr[lane * 8 + 2 * j + 1] * 0.5f);
        wz2[j] = pack2(Whz[lane * 8 + 2 * j] * 0.5f, Whz[lane * 8 + 2 * j + 1] * 0.5f);
        wn2[j] = pack2(Whn[lane * 8 + 2 * j],        Whn[lane * 8 + 2 * j + 1]);
        wa2[j] = pack2(Wout[lane * 8 + 2 * j] * L2E, Wout[lane * 8 + 2 * j + 1] * L2E);
        wb2[j] = (lane < 2)
               ? pack2(Wout[(8 + lane) * 8 + 2 * j] * L2E, Wout[(8 + lane) * 8 + 2 * j + 1] * L2E)
               : 0ull;
    }
    const u64 bhn2 = pack2(bhn[lane], 0.f);
    const u64 ba2  = pack2(bout[lane] * L2E, 0.f);
    const u64 bb2  = pack2((lane < 2) ? bout[8 + lane] * L2E : -1000.f, 0.f);  // ex2 -> 0

    __syncthreads();

    u64 h2[4] = {0ull, 0ull, 0ull, 0ull};   // h as 4 packed pairs
    float hown = 0.f;
    float accE = 0.f;   // sum of lg2(sum_exp) per step (replicated in group)
    float accT = 0.f;   // per-lane sum of target logits this lane owned

    const int src_base = tid & 24;           // warp-lane base of this group
    const int cls_b    = 8 + lane;           // second class this lane owns (only lanes 0,1 real)

    const int4* xp = reinterpret_cast<const int4*>(x_batch) + (size_t)b * (S_LEN / 4);
    int4 cur  = __ldg(xp);
    int carry = 0;                           // teacher-forced input at step 0 is 0

    for (int c = 0; c < S_LEN / 4; ++c) {
        const int4 nxt = (c + 1 < S_LEN / 4) ? __ldg(xp + c + 1) : make_int4(0, 0, 0, 0);
        const int pv[4] = {carry, cur.x, cur.y, cur.z};
        const int tv[4] = {cur.x, cur.y, cur.z, cur.w};

        #pragma unroll
        for (int u = 0; u < 4; ++u) {
            const int v = pv[u];
            const int t = tv[u];

            // ---- recurrence (critical chain) ----
            u64 ar = lutR2[v][lane];
            u64 az = lutZ2[v][lane];
            u64 an = bhn2;
            const float lnv = lutN[v][lane];
            #pragma unroll
            for (int j = 0; j < 4; ++j) {
                ar = fma2(wr2[j], h2[j], ar);
                az = fma2(wz2[j], h2[j], az);
                an = fma2(wn2[j], h2[j], an);
            }
            const float r = fmaf(0.5f, tanhfast(hadd2(ar)), 0.5f);
            const float z = fmaf(0.5f, tanhfast(hadd2(az)), 0.5f);
            const float n = tanhfast(fmaf(r, hadd2(an), lnv));
            hown = fmaf(z, hown - n, n);     // h_next = n + z*(h-n)

            // ---- barrier-free all-gather via 8 independent shuffles ----
            const float e0 = __shfl_sync(FULL, hown, src_base + 0);
            const float e1 = __shfl_sync(FULL, hown, src_base + 1);
            const float e2 = __shfl_sync(FULL, hown, src_base + 2);
            const float e3 = __shfl_sync(FULL, hown, src_base + 3);
            const float e4 = __shfl_sync(FULL, hown, src_base + 4);
            const float e5 = __shfl_sync(FULL, hown, src_base + 5);
            const float e6 = __shfl_sync(FULL, hown, src_base + 6);
            const float e7 = __shfl_sync(FULL, hown, src_base + 7);
            h2[0] = pack2(e0, e1);
            h2[1] = pack2(e2, e3);
            h2[2] = pack2(e4, e5);
            h2[3] = pack2(e6, e7);

            // ---- loss (off the recurrence chain) ----
            u64 aa = ba2, ab = bb2;
            #pragma unroll
            for (int j = 0; j < 4; ++j) {
                aa = fma2(wa2[j], h2[j], aa);
                ab = fma2(wb2[j], h2[j], ab);
            }
            const float la = hadd2(aa);
            const float lb = hadd2(ab);

            // target logit: accumulate locally on the owning lane (no shuffle)
            accT += (t == lane)  ? la : 0.f;
            accT += (t == cls_b) ? lb : 0.f;

            float e = ex2f(la) + ex2f(lb);
            e += __shfl_xor_sync(FULL, e, 1);
            e += __shfl_xor_sync(FULL, e, 2);
            e += __shfl_xor_sync(FULL, e, 4);
            accE += lg2f(e);
        }
        carry = cur.w;
        cur   = nxt;
    }

    // reduce accT across the 8-lane group, then combine with accE
    accT += __shfl_xor_sync(FULL, accT, 1);
    accT += __shfl_xor_sync(FULL, accT, 2);
    accT += __shfl_xor_sync(FULL, accT, 4);
    if (lane == 0) red[g] = accE - accT;
    __syncthreads();
    if (tid == 0) {
        float s = 0.f;
        #pragma unroll
        for (int i = 0; i < GPC; ++i) s += red[i];
        g_partials[blockIdx.x] = s;
    }
}

__global__ void reduce_kernel(float* __restrict__ out) {
    __shared__ float s[256];
    float v = 0.f;
    for (int i = threadIdx.x; i < NCTA; i += 256) v += g_partials[i];
    s[threadIdx.x] = v;
    __syncthreads();
    for (int off = 128; off; off >>= 1) {
        if (threadIdx.x < off) s[threadIdx.x] += s[threadIdx.x + off];
        __syncthreads();
    }
    if (threadIdx.x == 0)
        out[0] = s[0] * (float)(0.69314718055994530942 / ((double)S_LEN * (double)B_SZ));
}

extern "C" void kernel_launch(void* const* d_in, const int* in_sizes, int n_in,
                              void* d_out, int out_size)
{
    (void)in_sizes; (void)n_in; (void)out_size;
    const int*   x    = (const int*)  d_in[0];
    const float* Wir  = (const float*)d_in[1];
    const float* bir  = (const float*)d_in[2];
    const float* Wiz  = (const float*)d_in[3];
    const float* biz  = (const float*)d_in[4];
    const float* Win  = (const float*)d_in[5];
    const float* bin_ = (const float*)d_in[6];
    const float* Whr  = (const float*)d_in[7];
    const float* bhr  = (const float*)d_in[8];
    const float* Whz  = (const float*)d_in[9];
    const float* bhz  = (const float*)d_in[10];
    const float* Whn  = (const float*)d_in[11];
    const float* bhn  = (const float*)d_in[12];
    const float* Wout = (const float*)d_in[13];
    const float* bout = (const float*)d_in[14];

    gru_kernel<<<NCTA, TPB>>>(x, Wir, bir, Wiz, biz, Win, bin_,
                              Whr, bhr, Whz, bhz, Whn, bhn, Wout, bout);
    reduce_kernel<<<1, 256>>>((float*)d_out);
}

// round 6
// speedup vs baseline: 1.0014x; 1.0014x over previous
#include <cuda_runtime.h>

#define S_LEN 2048
#define B_SZ  8192
#define GPC   8                 // groups (batch elements) per CTA
#define TPB   (GPC * 8)         // 64 threads per CTA
#define NCTA  (B_SZ / GPC)      // 1024 CTAs

typedef unsigned long long u64;

__device__ float g_partials[NCTA];

__device__ __forceinline__ float ex2f(float x){ float y; asm("ex2.approx.f32 %0, %1;" : "=f"(y) : "f"(x)); return y; }
__device__ __forceinline__ float lg2f(float x){ float y; asm("lg2.approx.f32 %0, %1;" : "=f"(y) : "f"(x)); return y; }
__device__ __forceinline__ float tanhfast(float x){ float y; asm("tanh.approx.f32 %0, %1;" : "=f"(y) : "f"(x)); return y; }

// packed f32x2 fma (Blackwell): d = a*b + c elementwise on (lo,hi)
__device__ __forceinline__ u64 fma2(u64 a, u64 b, u64 c){
    u64 d; asm("fma.rn.f32x2 %0, %1, %2, %3;" : "=l"(d) : "l"(a), "l"(b), "l"(c)); return d;
}
__device__ __forceinline__ u64 pack2(float lo, float hi){
    u64 d; asm("mov.b64 %0, {%1, %2};" : "=l"(d) : "f"(lo), "f"(hi)); return d;
}
__device__ __forceinline__ float hadd2(u64 v){
    float lo, hi; asm("mov.b64 {%0, %1}, %2;" : "=f"(lo), "=f"(hi) : "l"(v)); return lo + hi;
}

__global__ __launch_bounds__(TPB) void gru_kernel(
    const int* __restrict__ x_batch,
    const float* __restrict__ Wir, const float* __restrict__ bir,
    const float* __restrict__ Wiz, const float* __restrict__ biz,
    const float* __restrict__ Win, const float* __restrict__ bin_,
    const float* __restrict__ Whr, const float* __restrict__ bhr,
    const float* __restrict__ Whz, const float* __restrict__ bhz,
    const float* __restrict__ Whn, const float* __restrict__ bhn,
    const float* __restrict__ Wout, const float* __restrict__ bout)
{
    // x-projection LUTs per count value v (0..9, padded to 16). R/Z entries
    // pre-packed as (val, 0) f32x2 to seed packed accumulators with one
    // LDS.64. Row stride 9 to spread banks across groups.
    __shared__ u64   lutR2[16][9];
    __shared__ u64   lutZ2[16][9];
    __shared__ float lutN [16][9];
    __shared__ float red[GPC];

    const int tid  = threadIdx.x;
    const int lane = tid & 7;            // hidden-unit row this thread owns
    const int g    = tid >> 3;           // group within CTA
    const int b    = blockIdx.x * GPC + g;
    const unsigned FULL = 0xffffffffu;

    const float L2E = 1.4426950408889634f;   // log2(e) (softmax fold)

    // ---- build LUTs (bits MSB-first). sigmoid(x)=0.5+0.5*tanh(x/2): fold 0.5 in.
    for (int i = tid; i < 16 * 8; i += TPB) {
        const int v = i >> 3;
        const int l = i & 7;
        float sr = 0.f, sz = 0.f, sn = 0.f;
        #pragma unroll
        for (int k = 0; k < 4; ++k)
            if ((v >> (3 - k)) & 1) {
                sr += Wir[l * 4 + k];
                sz += Wiz[l * 4 + k];
                sn += Win[l * 4 + k];
            }
        lutR2[v][l] = pack2((sr + bir[l] + bhr[l]) * 0.5f, 0.f);
        lutZ2[v][l] = pack2((sz + biz[l] + bhz[l]) * 0.5f, 0.f);
        lutN [v][l] = sn + bin_[l];
    }

    // ---- per-thread weights, packed across k-pairs ----
    u64 wr2[4], wz2[4], wn2[4], wa2[4], wb2[4];
    #pragma unroll
    for (int j = 0; j < 4; ++j) {
        wr2[j] = pack2(Whr[lane * 8 + 2 * j] * 0.5f, Whr[lane * 8 + 2 * j + 1] * 0.5f);
        wz2[j] = pack2(Whz[lane * 8 + 2 * j] * 0.5f, Whz[lane * 8 + 2 * j + 1] * 0.5f);
        wn2[j] = pack2(Whn[lane * 8 + 2 * j],        Whn[lane * 8 + 2 * j + 1]);
        wa2[j] = pack2(Wout[lane * 8 + 2 * j] * L2E, Wout[lane * 8 + 2 * j + 1] * L2E);
        wb2[j] = (lane < 2)
               ? pack2(Wout[(8 + lane) * 8 + 2 * j] * L2E, Wout[(8 + lane) * 8 + 2 * j + 1] * L2E)
               : 0ull;
    }
    const u64 bhn2 = pack2(bhn[lane], 0.f);
    const u64 ba2  = pack2(bout[lane] * L2E, 0.f);
    const u64 bb2  = pack2((lane < 2) ? bout[8 + lane] * L2E : -1000.f, 0.f);  // ex2 -> 0

    __syncthreads();

    u64 h2[4] = {0ull, 0ull, 0ull, 0ull};   // h as 4 packed pairs
    float hown = 0.f;
    float accE = 0.f;   // sum of lg2(sum_exp) per step (replicated in group)
    float accT = 0.f;   // per-lane sum of target logits this lane owned

    const int src_base = tid & 24;           // warp-lane base of this group
    const int cls_b    = 8 + lane;           // second class this lane owns (only lanes 0,1 real)

    const int4* xp = reinterpret_cast<const int4*>(x_batch) + (size_t)b * (S_LEN / 4);
    int4 cur  = __ldg(xp);
    int carry = 0;                           // teacher-forced input at step 0 is 0

    for (int c = 0; c < S_LEN / 4; ++c) {
        const int4 nxt = (c + 1 < S_LEN / 4) ? __ldg(xp + c + 1) : make_int4(0, 0, 0, 0);
        const int pv[4] = {carry, cur.x, cur.y, cur.z};
        const int tv[4] = {cur.x, cur.y, cur.z, cur.w};

        #pragma unroll
        for (int u = 0; u < 4; ++u) {
            const int v = pv[u];
            const int t = tv[u];

            // ---- recurrence (critical chain) ----
            u64 ar = lutR2[v][lane];
            u64 az = lutZ2[v][lane];
            u64 an = bhn2;
            const float lnv = lutN[v][lane];
            #pragma unroll
            for (int j = 0; j < 4; ++j) {
                ar = fma2(wr2[j], h2[j], ar);
                az = fma2(wz2[j], h2[j], az);
                an = fma2(wn2[j], h2[j], an);
            }
            const float r = fmaf(0.5f, tanhfast(hadd2(ar)), 0.5f);
            const float z = fmaf(0.5f, tanhfast(hadd2(az)), 0.5f);
            const float n = tanhfast(fmaf(r, hadd2(an), lnv));
            hown = fmaf(z, hown - n, n);     // h_next = n + z*(h-n)

            // ---- barrier-free all-gather via 8 independent shuffles ----
            const float e0 = __shfl_sync(FULL, hown, src_base + 0);
            const float e1 = __shfl_sync(FULL, hown, src_base + 1);
            const float e2 = __shfl_sync(FULL, hown, src_base + 2);
            const float e3 = __shfl_sync(FULL, hown, src_base + 3);
            const float e4 = __shfl_sync(FULL, hown, src_base + 4);
            const float e5 = __shfl_sync(FULL, hown, src_base + 5);
            const float e6 = __shfl_sync(FULL, hown, src_base + 6);
            const float e7 = __shfl_sync(FULL, hown, src_base + 7);
            h2[0] = pack2(e0, e1);
            h2[1] = pack2(e2, e3);
            h2[2] = pack2(e4, e5);
            h2[3] = pack2(e6, e7);

            // ---- loss (off the recurrence chain) ----
            u64 aa = ba2, ab = bb2;
            #pragma unroll
            for (int j = 0; j < 4; ++j) {
                aa = fma2(wa2[j], h2[j], aa);
                ab = fma2(wb2[j], h2[j], ab);
            }
            const float la = hadd2(aa);
            const float lb = hadd2(ab);

            // target logit: accumulate locally on the owning lane (no shuffle)
            accT += (t == lane)  ? la : 0.f;
            accT += (t == cls_b) ? lb : 0.f;

            float e = ex2f(la) + ex2f(lb);
            e += __shfl_xor_sync(FULL, e, 1);
            e += __shfl_xor_sync(FULL, e, 2);
            e += __shfl_xor_sync(FULL, e, 4);
            accE += lg2f(e);
        }
        carry = cur.w;
        cur   = nxt;
    }

    // reduce accT across the 8-lane group, then combine with accE
    accT += __shfl_xor_sync(FULL, accT, 1);
    accT += __shfl_xor_sync(FULL, accT, 2);
    accT += __shfl_xor_sync(FULL, accT, 4);
    if (lane == 0) red[g] = accE - accT;
    __syncthreads();
    if (tid == 0) {
        float s = 0.f;
        #pragma unroll
        for (int i = 0; i < GPC; ++i) s += red[i];
        g_partials[blockIdx.x] = s;
    }
}

__global__ void reduce_kernel(float* __restrict__ out) {
    __shared__ float s[256];
    float v = 0.f;
    for (int i = threadIdx.x; i < NCTA; i += 256) v += g_partials[i];
    s[threadIdx.x] = v;
    __syncthreads();
    for (int off = 128; off; off >>= 1) {
        if (threadIdx.x < off) s[threadIdx.x] += s[threadIdx.x + off];
        __syncthreads();
    }
    if (threadIdx.x == 0)
        out[0] = s[0] * (float)(0.69314718055994530942 / ((double)S_LEN * (double)B_SZ));
}

extern "C" void kernel_launch(void* const* d_in, const int* in_sizes, int n_in,
                              void* d_out, int out_size)
{
    (void)in_sizes; (void)n_in; (void)out_size;
    const int*   x    = (const int*)  d_in[0];
    const float* Wir  = (const float*)d_in[1];
    const float* bir  = (const float*)d_in[2];
    const float* Wiz  = (const float*)d_in[3];
    const float* biz  = (const float*)d_in[4];
    const float* Win  = (const float*)d_in[5];
    const float* bin_ = (const float*)d_in[6];
    const float* Whr  = (const float*)d_in[7];
    const float* bhr  = (const float*)d_in[8];
    const float* Whz  = (const float*)d_in[9];
    const float* bhz  = (const float*)d_in[10];
    const float* Whn  = (const float*)d_in[11];
    const float* bhn  = (const float*)d_in[12];
    const float* Wout = (const float*)d_in[13];
    const float* bout = (const float*)d_in[14];

    gru_kernel<<<NCTA, TPB>>>(x, Wir, bir, Wiz, biz, Win, bin_,
                              Whr, bhr, Whz, bhz, Whn, bhn, Wout, bout);
    reduce_kernel<<<1, 256>>>((float*)d_out);
}